// round 1
// baseline (speedup 1.0000x reference)
#include <cuda_runtime.h>
#include <cstdint>

#define NN 100000
#define NE_CAP 1600000
#define NF 128
#define FO3 40

// Scratch (device globals: no allocation allowed in kernel_launch)
__device__ float g_dinv[NN];
__device__ float g_h[(size_t)NN * NF];
__device__ float g_y[(size_t)NN * NF];
__device__ int   g_src[NE_CAP];
__device__ int   g_dst[NE_CAP];
__device__ int   g_is32;

// ---------------- edge index dtype detect + convert ----------------
__global__ void k_flag_init() { g_is32 = 0; }

__global__ void k_detect(const long long* __restrict__ raw, int nE) {
    int i = blockIdx.x * blockDim.x + threadIdx.x;
    int lim = nE < 4096 ? nE : 4096;
    if (i < lim) {
        long long v = raw[i];
        if (v < 0 || v >= (1LL << 30)) atomicOr(&g_is32, 1);
    }
}

__global__ void k_cvt(const void* __restrict__ raw, int nE) {
    int i = blockIdx.x * blockDim.x + threadIdx.x;
    if (i >= nE) return;
    if (g_is32) {
        const int* p = (const int*)raw;
        g_src[i] = p[i];
        g_dst[i] = p[(size_t)nE + i];
    } else {
        const long long* p = (const long long*)raw;
        g_src[i] = (int)p[i];
        g_dst[i] = (int)p[(size_t)nE + i];
    }
}

// ---------------- degree / dinv ----------------
__global__ void k_deg_init(float* deg, int n) {
    int i = blockIdx.x * blockDim.x + threadIdx.x;
    if (i < n) deg[i] = 1.0f;  // self-loop weight
}

__global__ void k_deg_edges(const float* __restrict__ ew, float* deg, int nE) {
    int e = blockIdx.x * blockDim.x + threadIdx.x;
    if (e < nE) atomicAdd(&deg[g_dst[e]], ew[e]);
}

__global__ void k_dinv(float* deg, int n) {
    int i = blockIdx.x * blockDim.x + threadIdx.x;
    if (i < n) deg[i] = rsqrtf(deg[i]);  // deg >= 1 always
}

// ---------------- GEMM: H = (RELU? max(X,0):X) @ W ----------------
// fout = 128. Block: 256 threads = 8 warps, 8 rows/warp = 64 rows/block.
// W fully staged in smem (64KB), X rows staged per-warp (32KB).
template <bool RELU>
__global__ void k_gemm128(const float* __restrict__ X, const float* __restrict__ W,
                          float* __restrict__ H, int n) {
    extern __shared__ float sm[];
    float* Ws = sm;            // 128*128
    float* Xs = sm + NF * NF;  // 8 warps * 8 rows * 128
    int tid = threadIdx.x, warp = tid >> 5, lane = tid & 31;

    for (int i = tid; i < NF * NF; i += 256) Ws[i] = W[i];

    int row0 = blockIdx.x * 64 + warp * 8;
    float* xs = Xs + warp * (8 * NF);
#pragma unroll
    for (int r = 0; r < 8; r++) {
        int row = row0 + r;
        float4 v = make_float4(0.f, 0.f, 0.f, 0.f);
        if (row < n) v = ((const float4*)(X + (size_t)row * NF))[lane];
        if (RELU) {
            v.x = fmaxf(v.x, 0.f); v.y = fmaxf(v.y, 0.f);
            v.z = fmaxf(v.z, 0.f); v.w = fmaxf(v.w, 0.f);
        }
        ((float4*)(xs + r * NF))[lane] = v;
    }
    __syncthreads();

    float4 acc[8];
#pragma unroll
    for (int r = 0; r < 8; r++) acc[r] = make_float4(0.f, 0.f, 0.f, 0.f);

#pragma unroll 4
    for (int k = 0; k < NF; k++) {
        float4 w4 = ((const float4*)(Ws + k * NF))[lane];
#pragma unroll
        for (int r = 0; r < 8; r++) {
            float xk = xs[r * NF + k];
            acc[r].x = fmaf(xk, w4.x, acc[r].x);
            acc[r].y = fmaf(xk, w4.y, acc[r].y);
            acc[r].z = fmaf(xk, w4.z, acc[r].z);
            acc[r].w = fmaf(xk, w4.w, acc[r].w);
        }
    }
#pragma unroll
    for (int r = 0; r < 8; r++) {
        int row = row0 + r;
        if (row < n) ((float4*)(H + (size_t)row * NF))[lane] = acc[r];
    }
}

// fout = 40 variant. Lane covers col `lane`, and col `32+lane` for lane<8.
template <bool RELU>
__global__ void k_gemm40(const float* __restrict__ X, const float* __restrict__ W,
                         float* __restrict__ H, int n) {
    extern __shared__ float sm[];
    float* Ws = sm;             // 128*40
    float* Xs = sm + NF * FO3;  // 8*8*128
    int tid = threadIdx.x, warp = tid >> 5, lane = tid & 31;

    for (int i = tid; i < NF * FO3; i += 256) Ws[i] = W[i];

    int row0 = blockIdx.x * 64 + warp * 8;
    float* xs = Xs + warp * (8 * NF);
#pragma unroll
    for (int r = 0; r < 8; r++) {
        int row = row0 + r;
        float4 v = make_float4(0.f, 0.f, 0.f, 0.f);
        if (row < n) v = ((const float4*)(X + (size_t)row * NF))[lane];
        if (RELU) {
            v.x = fmaxf(v.x, 0.f); v.y = fmaxf(v.y, 0.f);
            v.z = fmaxf(v.z, 0.f); v.w = fmaxf(v.w, 0.f);
        }
        ((float4*)(xs + r * NF))[lane] = v;
    }
    __syncthreads();

    float a0[8], a1[8];
#pragma unroll
    for (int r = 0; r < 8; r++) { a0[r] = 0.f; a1[r] = 0.f; }
    bool hi = lane < 8;

#pragma unroll 4
    for (int k = 0; k < NF; k++) {
        float w0 = Ws[k * FO3 + lane];
        float w1 = hi ? Ws[k * FO3 + 32 + lane] : 0.f;
#pragma unroll
        for (int r = 0; r < 8; r++) {
            float xk = xs[r * NF + k];
            a0[r] = fmaf(xk, w0, a0[r]);
            a1[r] = fmaf(xk, w1, a1[r]);
        }
    }
#pragma unroll
    for (int r = 0; r < 8; r++) {
        int row = row0 + r;
        if (row < n) {
            H[(size_t)row * FO3 + lane] = a0[r];
            if (hi) H[(size_t)row * FO3 + 32 + lane] = a1[r];
        }
    }
}

// ---------------- out init: out = b + h * dinv^2 (self-loop + bias) ----------------
__global__ void k_init(const float* __restrict__ h, const float* __restrict__ b,
                       const float* __restrict__ dinv, float* __restrict__ out,
                       int n, int fout) {
    long long i = (long long)blockIdx.x * blockDim.x + threadIdx.x;
    long long tot = (long long)n * fout;
    if (i >= tot) return;
    int node = (int)(i / fout);
    int c = (int)(i - (long long)node * fout);
    float dv = dinv[node];
    out[i] = b[c] + h[i] * dv * dv;
}

// ---------------- scatter: out[dst] += h[src] * (dinv[src]*w*dinv[dst]) ----------------
// One thread per (edge, 4-col group). Vectorized reductions via red.global.add.v4.f32.
__global__ void k_scatter(const float* __restrict__ ew, const float* __restrict__ dinv,
                          const float* __restrict__ h, float* __restrict__ out,
                          int nE, int fout) {
    int ng = fout >> 2;
    long long t = (long long)blockIdx.x * blockDim.x + threadIdx.x;
    long long total = (long long)nE * ng;
    if (t >= total) return;
    int e = (int)(t / ng);
    int g = (int)(t - (long long)e * ng);
    int s = g_src[e];
    int d = g_dst[e];
    float norm = ew[e] * dinv[s] * dinv[d];
    const float4 hv = *(const float4*)(h + (size_t)s * fout + (g << 2));
    float* o = out + (size_t)d * fout + (g << 2);
    asm volatile("red.global.add.v4.f32 [%0], {%1, %2, %3, %4};"
                 :: "l"(o), "f"(hv.x * norm), "f"(hv.y * norm),
                    "f"(hv.z * norm), "f"(hv.w * norm)
                 : "memory");
}

// ---------------- launch ----------------
extern "C" void kernel_launch(void* const* d_in, const int* in_sizes, int n_in,
                              void* d_out, int out_size) {
    const float*     x   = (const float*)d_in[0];
    const void*      ei  = d_in[1];
    const float*     ew  = (const float*)d_in[2];
    const float*     W1  = (const float*)d_in[3];
    const float*     b1  = (const float*)d_in[4];
    const float*     W2  = (const float*)d_in[5];
    const float*     b2  = (const float*)d_in[6];
    const float*     W3  = (const float*)d_in[7];
    const float*     b3  = (const float*)d_in[8];
    int n  = in_sizes[0] / NF;
    int nE = in_sizes[2];
    float* out = (float*)d_out;

    float *dinv, *h, *y;
    cudaGetSymbolAddress((void**)&dinv, g_dinv);
    cudaGetSymbolAddress((void**)&h, g_h);
    cudaGetSymbolAddress((void**)&y, g_y);

    const int T = 256;
    size_t smem128 = (size_t)(NF * NF + 8 * 8 * NF) * sizeof(float);  // 96 KB
    size_t smem40  = (size_t)(NF * FO3 + 8 * 8 * NF) * sizeof(float); // 52 KB
    cudaFuncSetAttribute(k_gemm128<false>, cudaFuncAttributeMaxDynamicSharedMemorySize, (int)smem128);
    cudaFuncSetAttribute(k_gemm128<true>,  cudaFuncAttributeMaxDynamicSharedMemorySize, (int)smem128);
    cudaFuncSetAttribute(k_gemm40<true>,   cudaFuncAttributeMaxDynamicSharedMemorySize, (int)smem40);

    // Edge index dtype detection + conversion to int32 arrays
    k_flag_init<<<1, 1>>>();
    k_detect<<<(4096 + T - 1) / T, T>>>((const long long*)ei, nE);
    k_cvt<<<(nE + T - 1) / T, T>>>(ei, nE);

    // Degree + dinv (shared by all layers)
    k_deg_init<<<(n + T - 1) / T, T>>>(dinv, n);
    k_deg_edges<<<(nE + T - 1) / T, T>>>(ew, dinv, nE);
    k_dinv<<<(n + T - 1) / T, T>>>(dinv, n);

    int gb = (n + 63) / 64;
    long long tot128 = (long long)n * NF;
    long long sc128  = (long long)nE * 32;
    long long tot40  = (long long)n * FO3;
    long long sc40   = (long long)nE * 10;

    // Layer 1
    k_gemm128<false><<<gb, T, smem128>>>(x, W1, h, n);
    k_init<<<(int)((tot128 + T - 1) / T), T>>>(h, b1, dinv, y, n, NF);
    k_scatter<<<(int)((sc128 + T - 1) / T), T>>>(ew, dinv, h, y, nE, NF);

    // Layer 2 (ReLU of layer-1 output fused into GEMM's X load)
    k_gemm128<true><<<gb, T, smem128>>>(y, W2, h, n);
    k_init<<<(int)((tot128 + T - 1) / T), T>>>(h, b2, dinv, y, n, NF);
    k_scatter<<<(int)((sc128 + T - 1) / T), T>>>(ew, dinv, h, y, nE, NF);

    // Layer 3 (fout = 40, no trailing activation), writes d_out
    k_gemm40<true><<<gb, T, smem40>>>(y, W3, h, n);
    k_init<<<(int)((tot40 + T - 1) / T), T>>>(h, b3, dinv, out, n, FO3);
    k_scatter<<<(int)((sc40 + T - 1) / T), T>>>(ew, dinv, h, out, nE, FO3);
}

// round 2
// speedup vs baseline: 1.5457x; 1.5457x over previous
#include <cuda_runtime.h>
#include <cstdint>

#define NN 100000
#define NE_CAP 1600000
#define NF 128
#define FO3 40

// ---------------- device scratch (no allocs allowed) ----------------
__device__ float g_dinv[NN];
__device__ float g_h[(size_t)NN * NF];
__device__ float g_y[(size_t)NN * NF];
__device__ int   g_src[NE_CAP];
__device__ int   g_dst[NE_CAP];
__device__ int   g_esrc[NE_CAP];    // CSR-by-dst: source node per sorted edge
__device__ float g_enorm[NE_CAP];   // CSR-by-dst: precomputed edge norm
__device__ int   g_rowptr[NN + 1];
__device__ int   g_cur[NN];
__device__ int   g_cnt[NN];
__device__ int   g_bsum[1024];
__device__ int   g_is32;

// ---------------- f32x2 helpers (sm_103a FFMA2) ----------------
__device__ __forceinline__ void ffma2(unsigned long long& d,
                                      unsigned long long a, unsigned long long b) {
    asm("fma.rn.f32x2 %0, %1, %2, %0;" : "+l"(d) : "l"(a), "l"(b));
}
__device__ __forceinline__ unsigned long long pk2(float lo, float hi) {
    unsigned long long r;
    asm("mov.b64 %0, {%1, %2};" : "=l"(r) : "f"(lo), "f"(hi));
    return r;
}
__device__ __forceinline__ float2 upk2(unsigned long long v) {
    float2 r;
    asm("mov.b64 {%0, %1}, %2;" : "=f"(r.x), "=f"(r.y) : "l"(v));
    return r;
}

// ---------------- edge index dtype detect + convert ----------------
__global__ void k_flag_init() { g_is32 = 0; }

__global__ void k_detect(const long long* __restrict__ raw, int nE) {
    int i = blockIdx.x * blockDim.x + threadIdx.x;
    int lim = nE < 4096 ? nE : 4096;
    if (i < lim) {
        long long v = raw[i];
        if (v < 0 || v >= (1LL << 30)) atomicOr(&g_is32, 1);
    }
}

__global__ void k_cvt(const void* __restrict__ raw, int nE) {
    int i = blockIdx.x * blockDim.x + threadIdx.x;
    if (i >= nE) return;
    if (g_is32) {
        const int* p = (const int*)raw;
        g_src[i] = p[i];
        g_dst[i] = p[(size_t)nE + i];
    } else {
        const long long* p = (const long long*)raw;
        g_src[i] = (int)p[i];
        g_dst[i] = (int)p[(size_t)nE + i];
    }
}

// ---------------- degree + indegree count ----------------
__global__ void k_init0(float* deg, int* cnt, int n) {
    int i = blockIdx.x * blockDim.x + threadIdx.x;
    if (i < n) { deg[i] = 1.0f; cnt[i] = 0; }  // self-loop weight = 1
}

__global__ void k_prep(const float* __restrict__ ew, float* deg, int* cnt, int nE) {
    int e = blockIdx.x * blockDim.x + threadIdx.x;
    if (e < nE) {
        int d = g_dst[e];
        atomicAdd(&deg[d], ew[e]);
        atomicAdd(&cnt[d], 1);
    }
}

__global__ void k_dinv(float* deg, int n) {
    int i = blockIdx.x * blockDim.x + threadIdx.x;
    if (i < n) deg[i] = rsqrtf(deg[i]);  // deg >= 1 always
}

// ---------------- exclusive scan of cnt -> rowptr ----------------
__global__ void k_scanA(const int* __restrict__ cnt, int* rowptr, int* bsum, int n) {
    __shared__ int s[1024];
    int t = threadIdx.x, i = blockIdx.x * 1024 + t;
    int v = (i < n) ? cnt[i] : 0;
    s[t] = v;
    __syncthreads();
#pragma unroll
    for (int off = 1; off < 1024; off <<= 1) {
        int x = (t >= off) ? s[t - off] : 0;
        __syncthreads();
        s[t] += x;
        __syncthreads();
    }
    if (i < n) rowptr[i] = s[t] - v;  // exclusive within block
    if (t == 1023) bsum[blockIdx.x] = s[1023];
}

__global__ void k_scanB(int* bsum, int nb) {  // serial, nb ~ 98
    if (threadIdx.x == 0) {
        int run = 0;
        for (int i = 0; i < nb; i++) { int v = bsum[i]; bsum[i] = run; run += v; }
    }
}

__global__ void k_scanC(int* rowptr, const int* __restrict__ bsum, int* cur,
                        int n, int nE) {
    int i = blockIdx.x * blockDim.x + threadIdx.x;
    if (i < n) {
        int v = rowptr[i] + bsum[i >> 10];
        rowptr[i] = v;
        cur[i] = v;
    }
    if (i == 0) rowptr[n] = nE;
}

// ---------------- place edges into CSR-by-dst with precomputed norm ----------------
__global__ void k_place(const float* __restrict__ ew, const float* __restrict__ dinv,
                        int nE) {
    int e = blockIdx.x * blockDim.x + threadIdx.x;
    if (e >= nE) return;
    int s = g_src[e], d = g_dst[e];
    int p = atomicAdd(&g_cur[d], 1);
    g_esrc[p] = s;
    g_enorm[p] = ew[e] * dinv[s] * dinv[d];
}

// ---------------- GEMM: H = (RELU? max(X,0):X) @ W  (fout=128), FFMA2 ----------------
// 256 threads = 8 warps, 8 rows/warp. W in smem (64KB). X rows staged DUPLICATED
// (each x value stored twice, adjacent) so the k-loop reads b64 broadcasts directly.
template <bool RELU>
__global__ void k_gemm128(const float* __restrict__ X, const float* __restrict__ W,
                          float* __restrict__ H, int n) {
    extern __shared__ float sm[];
    float* Ws = sm;            // 128*128
    float* Xs = sm + NF * NF;  // 8 warps * 8 rows * 256 (dup)
    int tid = threadIdx.x, warp = tid >> 5, lane = tid & 31;

    for (int i = tid; i < NF * NF; i += 256) Ws[i] = W[i];

    int row0 = blockIdx.x * 64 + warp * 8;
    float* xs = Xs + warp * (8 * 2 * NF);
#pragma unroll
    for (int r = 0; r < 8; r++) {
        int row = row0 + r;
        float4 v = make_float4(0.f, 0.f, 0.f, 0.f);
        if (row < n) v = ((const float4*)(X + (size_t)row * NF))[lane];
        if (RELU) {
            v.x = fmaxf(v.x, 0.f); v.y = fmaxf(v.y, 0.f);
            v.z = fmaxf(v.z, 0.f); v.w = fmaxf(v.w, 0.f);
        }
        float4* dst = (float4*)(xs + r * 2 * NF) + 2 * lane;
        dst[0] = make_float4(v.x, v.x, v.y, v.y);
        dst[1] = make_float4(v.z, v.z, v.w, v.w);
    }
    __syncthreads();

    unsigned long long acc[8][2];
#pragma unroll
    for (int r = 0; r < 8; r++) { acc[r][0] = 0ull; acc[r][1] = 0ull; }

#pragma unroll 4
    for (int k = 0; k < NF; k++) {
        float4 wv = ((const float4*)(Ws + k * NF))[lane];
        unsigned long long w01 = pk2(wv.x, wv.y);
        unsigned long long w23 = pk2(wv.z, wv.w);
#pragma unroll
        for (int r = 0; r < 8; r++) {
            unsigned long long xk2 =
                *(const unsigned long long*)(xs + r * 2 * NF + 2 * k);
            ffma2(acc[r][0], xk2, w01);
            ffma2(acc[r][1], xk2, w23);
        }
    }
#pragma unroll
    for (int r = 0; r < 8; r++) {
        int row = row0 + r;
        if (row < n) {
            float2 a = upk2(acc[r][0]), b = upk2(acc[r][1]);
            ((float4*)(H + (size_t)row * NF))[lane] = make_float4(a.x, a.y, b.x, b.y);
        }
    }
}

// fout = 40 variant: lane c (<20) owns col pair (2c, 2c+1).
template <bool RELU>
__global__ void k_gemm40(const float* __restrict__ X, const float* __restrict__ W,
                         float* __restrict__ H, int n) {
    extern __shared__ float sm[];
    float* Ws = sm;             // 128*40
    float* Xs = sm + NF * FO3;  // 8 warps * 8 rows * 256 (dup)
    int tid = threadIdx.x, warp = tid >> 5, lane = tid & 31;

    for (int i = tid; i < NF * FO3; i += 256) Ws[i] = W[i];

    int row0 = blockIdx.x * 64 + warp * 8;
    float* xs = Xs + warp * (8 * 2 * NF);
#pragma unroll
    for (int r = 0; r < 8; r++) {
        int row = row0 + r;
        float4 v = make_float4(0.f, 0.f, 0.f, 0.f);
        if (row < n) v = ((const float4*)(X + (size_t)row * NF))[lane];
        if (RELU) {
            v.x = fmaxf(v.x, 0.f); v.y = fmaxf(v.y, 0.f);
            v.z = fmaxf(v.z, 0.f); v.w = fmaxf(v.w, 0.f);
        }
        float4* dst = (float4*)(xs + r * 2 * NF) + 2 * lane;
        dst[0] = make_float4(v.x, v.x, v.y, v.y);
        dst[1] = make_float4(v.z, v.z, v.w, v.w);
    }
    __syncthreads();

    if (lane < 20) {
        unsigned long long acc[8];
#pragma unroll
        for (int r = 0; r < 8; r++) acc[r] = 0ull;

#pragma unroll 4
        for (int k = 0; k < NF; k++) {
            unsigned long long w2 =
                *(const unsigned long long*)(Ws + k * FO3 + 2 * lane);
#pragma unroll
            for (int r = 0; r < 8; r++) {
                unsigned long long xk2 =
                    *(const unsigned long long*)(xs + r * 2 * NF + 2 * k);
                ffma2(acc[r], xk2, w2);
            }
        }
#pragma unroll
        for (int r = 0; r < 8; r++) {
            int row = row0 + r;
            if (row < n) {
                float2 a = upk2(acc[r]);
                *(float2*)(H + (size_t)row * FO3 + 2 * lane) = a;
            }
        }
    }
}

// ---------------- aggregation (CSR gather): out[d] = b + self + sum_e norm*h[src] ----
__global__ void k_agg128(const float* __restrict__ h, const float* __restrict__ bias,
                         const float* __restrict__ dinv, float* __restrict__ out,
                         int n) {
    int w = (blockIdx.x * blockDim.x + threadIdx.x) >> 5;
    int lane = threadIdx.x & 31;
    if (w >= n) return;
    int d = w;
    const float4* h4 = (const float4*)h;
    float dv = dinv[d];
    float selfn = dv * dv;
    float4 acc = h4[(size_t)d * 32 + lane];
    acc.x *= selfn; acc.y *= selfn; acc.z *= selfn; acc.w *= selfn;

    int p = g_rowptr[d], p1 = g_rowptr[d + 1];
    for (; p + 2 <= p1; p += 2) {
        int s0 = g_esrc[p], s1 = g_esrc[p + 1];
        float n0 = g_enorm[p], n1 = g_enorm[p + 1];
        float4 a = h4[(size_t)s0 * 32 + lane];
        float4 b = h4[(size_t)s1 * 32 + lane];
        acc.x = fmaf(a.x, n0, acc.x); acc.x = fmaf(b.x, n1, acc.x);
        acc.y = fmaf(a.y, n0, acc.y); acc.y = fmaf(b.y, n1, acc.y);
        acc.z = fmaf(a.z, n0, acc.z); acc.z = fmaf(b.z, n1, acc.z);
        acc.w = fmaf(a.w, n0, acc.w); acc.w = fmaf(b.w, n1, acc.w);
    }
    if (p < p1) {
        int s0 = g_esrc[p];
        float n0 = g_enorm[p];
        float4 a = h4[(size_t)s0 * 32 + lane];
        acc.x = fmaf(a.x, n0, acc.x); acc.y = fmaf(a.y, n0, acc.y);
        acc.z = fmaf(a.z, n0, acc.z); acc.w = fmaf(a.w, n0, acc.w);
    }
    float4 bv = ((const float4*)bias)[lane];
    acc.x += bv.x; acc.y += bv.y; acc.z += bv.z; acc.w += bv.w;
    ((float4*)out)[(size_t)d * 32 + lane] = acc;
}

__global__ void k_agg40(const float* __restrict__ h, const float* __restrict__ bias,
                        const float* __restrict__ dinv, float* __restrict__ out,
                        int n) {
    int w = (blockIdx.x * blockDim.x + threadIdx.x) >> 5;
    int lane = threadIdx.x & 31;
    if (w >= n || lane >= 20) return;
    int d = w;
    const float2* h2 = (const float2*)h;
    float dv = dinv[d];
    float selfn = dv * dv;
    float2 acc = h2[(size_t)d * 20 + lane];
    acc.x *= selfn; acc.y *= selfn;

    int p = g_rowptr[d], p1 = g_rowptr[d + 1];
    for (; p + 2 <= p1; p += 2) {
        int s0 = g_esrc[p], s1 = g_esrc[p + 1];
        float n0 = g_enorm[p], n1 = g_enorm[p + 1];
        float2 a = h2[(size_t)s0 * 20 + lane];
        float2 b = h2[(size_t)s1 * 20 + lane];
        acc.x = fmaf(a.x, n0, acc.x); acc.x = fmaf(b.x, n1, acc.x);
        acc.y = fmaf(a.y, n0, acc.y); acc.y = fmaf(b.y, n1, acc.y);
    }
    if (p < p1) {
        int s0 = g_esrc[p];
        float n0 = g_enorm[p];
        float2 a = h2[(size_t)s0 * 20 + lane];
        acc.x = fmaf(a.x, n0, acc.x); acc.y = fmaf(a.y, n0, acc.y);
    }
    float2 bv = ((const float2*)bias)[lane];
    acc.x += bv.x; acc.y += bv.y;
    ((float2*)out)[(size_t)d * 20 + lane] = acc;
}

// ---------------- launch ----------------
extern "C" void kernel_launch(void* const* d_in, const int* in_sizes, int n_in,
                              void* d_out, int out_size) {
    const float* x  = (const float*)d_in[0];
    const void*  ei = d_in[1];
    const float* ew = (const float*)d_in[2];
    const float* W1 = (const float*)d_in[3];
    const float* b1 = (const float*)d_in[4];
    const float* W2 = (const float*)d_in[5];
    const float* b2 = (const float*)d_in[6];
    const float* W3 = (const float*)d_in[7];
    const float* b3 = (const float*)d_in[8];
    int n  = in_sizes[0] / NF;
    int nE = in_sizes[2];
    float* out = (float*)d_out;

    float *dinv, *h, *y;
    int *rowptr, *cur, *cnt, *bsum;
    cudaGetSymbolAddress((void**)&dinv, g_dinv);
    cudaGetSymbolAddress((void**)&h, g_h);
    cudaGetSymbolAddress((void**)&y, g_y);
    cudaGetSymbolAddress((void**)&rowptr, g_rowptr);
    cudaGetSymbolAddress((void**)&cur, g_cur);
    cudaGetSymbolAddress((void**)&cnt, g_cnt);
    cudaGetSymbolAddress((void**)&bsum, g_bsum);

    const int T = 256;
    size_t smem128 = (size_t)(NF * NF + 8 * 8 * 2 * NF) * sizeof(float);   // 128 KB
    size_t smem40  = (size_t)(NF * FO3 + 8 * 8 * 2 * NF) * sizeof(float);  // ~84 KB
    cudaFuncSetAttribute(k_gemm128<false>, cudaFuncAttributeMaxDynamicSharedMemorySize, (int)smem128);
    cudaFuncSetAttribute(k_gemm128<true>,  cudaFuncAttributeMaxDynamicSharedMemorySize, (int)smem128);
    cudaFuncSetAttribute(k_gemm40<true>,   cudaFuncAttributeMaxDynamicSharedMemorySize, (int)smem40);

    // Edge dtype detect + convert
    k_flag_init<<<1, 1>>>();
    k_detect<<<(4096 + T - 1) / T, T>>>((const long long*)ei, nE);
    k_cvt<<<(nE + T - 1) / T, T>>>(ei, nE);

    // Degree (weighted, w/ self loop) + in-degree counts
    k_init0<<<(n + T - 1) / T, T>>>(dinv, cnt, n);
    k_prep<<<(nE + T - 1) / T, T>>>(ew, dinv, cnt, nE);
    k_dinv<<<(n + T - 1) / T, T>>>(dinv, n);

    // CSR build: exclusive scan + placement (norm precomputed, reused 3x)
    int nb = (n + 1023) / 1024;
    k_scanA<<<nb, 1024>>>(cnt, rowptr, bsum, n);
    k_scanB<<<1, 32>>>(bsum, nb);
    k_scanC<<<(n + T - 1) / T, T>>>(rowptr, bsum, cur, n, nE);
    k_place<<<(nE + T - 1) / T, T>>>(ew, dinv, nE);

    int gb = (n + 63) / 64;            // GEMM blocks (64 rows each)
    int ab = (n + 7) / 8;              // agg blocks (8 warps = 8 nodes each)

    // Layer 1
    k_gemm128<false><<<gb, T, smem128>>>(x, W1, h, n);
    k_agg128<<<ab, T>>>(h, b1, dinv, y, n);
    // Layer 2 (ReLU fused into GEMM X load)
    k_gemm128<true><<<gb, T, smem128>>>(y, W2, h, n);
    k_agg128<<<ab, T>>>(h, b2, dinv, y, n);
    // Layer 3 (fout=40), writes d_out
    k_gemm40<true><<<gb, T, smem40>>>(y, W3, h, n);
    k_agg40<<<ab, T>>>(h, b3, dinv, out, n);
}

// round 3
// speedup vs baseline: 2.0481x; 1.3251x over previous
#include <cuda_runtime.h>
#include <cstdint>

#define NN 100000
#define NE_CAP 1600000
#define NF 128
#define FO3 40

typedef unsigned long long u64;

// ---------------- device scratch (no allocs allowed) ----------------
__device__ float g_dinv[NN];
__device__ float g_h[(size_t)NN * NF];
__device__ float g_y[(size_t)NN * NF];
__device__ int   g_src[NE_CAP];
__device__ int   g_dst[NE_CAP];
__device__ int2  g_epack[NE_CAP];   // CSR-by-dst: {src, f32-bits norm}
__device__ int   g_rowptr[NN + 1];
__device__ int   g_cur[NN];
__device__ int   g_cnt[NN];
__device__ int   g_bsum[1024];
__device__ int   g_is32;

// ---------------- f32x2 helpers (sm_103a FFMA2) ----------------
__device__ __forceinline__ void ffma2(u64& d, u64 a, u64 b) {
    asm("fma.rn.f32x2 %0, %1, %2, %0;" : "+l"(d) : "l"(a), "l"(b));
}
__device__ __forceinline__ u64 dup2(float x) {
    u64 r;
    asm("mov.b64 %0, {%1, %1};" : "=l"(r) : "f"(x));
    return r;
}
__device__ __forceinline__ float2 upk2(u64 v) {
    float2 r;
    asm("mov.b64 {%0, %1}, %2;" : "=f"(r.x), "=f"(r.y) : "l"(v));
    return r;
}

// ---------------- edge dtype detect ----------------
__global__ void k_flag_init() { g_is32 = 0; }

__global__ void k_detect(const long long* __restrict__ raw, int nE) {
    int i = blockIdx.x * blockDim.x + threadIdx.x;
    int lim = nE < 4096 ? nE : 4096;
    if (i < lim) {
        long long v = raw[i];
        if (v < 0 || v >= (1LL << 30)) atomicOr(&g_is32, 1);
    }
}

// ---------------- deg=1, cnt=0 ----------------
__global__ void k_init0(float* deg, int* cnt, int n) {
    int i = blockIdx.x * blockDim.x + threadIdx.x;
    if (i < n) { deg[i] = 1.0f; cnt[i] = 0; }
}

// ---------------- fused convert + degree + count ----------------
__global__ void k_prep(const void* __restrict__ raw, const float* __restrict__ ew,
                       float* deg, int* cnt, int nE) {
    int e = blockIdx.x * blockDim.x + threadIdx.x;
    if (e >= nE) return;
    int s, d;
    if (g_is32) {
        const int* p = (const int*)raw;
        s = p[e]; d = p[(size_t)nE + e];
    } else {
        const long long* p = (const long long*)raw;
        s = (int)p[e]; d = (int)p[(size_t)nE + e];
    }
    g_src[e] = s;
    g_dst[e] = d;
    atomicAdd(&deg[d], ew[e]);
    atomicAdd(&cnt[d], 1);
}

__global__ void k_dinv(float* deg, int n) {
    int i = blockIdx.x * blockDim.x + threadIdx.x;
    if (i < n) deg[i] = rsqrtf(deg[i]);
}

// ---------------- exclusive scan cnt -> rowptr ----------------
__global__ void k_scanA(const int* __restrict__ cnt, int* rowptr, int* bsum, int n) {
    __shared__ int s[1024];
    int t = threadIdx.x, i = blockIdx.x * 1024 + t;
    int v = (i < n) ? cnt[i] : 0;
    s[t] = v;
    __syncthreads();
#pragma unroll
    for (int off = 1; off < 1024; off <<= 1) {
        int x = (t >= off) ? s[t - off] : 0;
        __syncthreads();
        s[t] += x;
        __syncthreads();
    }
    if (i < n) rowptr[i] = s[t] - v;
    if (t == 1023) bsum[blockIdx.x] = s[1023];
}

__global__ void k_scanB(int* bsum, int nb) {
    if (threadIdx.x == 0) {
        int run = 0;
        for (int i = 0; i < nb; i++) { int v = bsum[i]; bsum[i] = run; run += v; }
    }
}

__global__ void k_scanC(int* rowptr, const int* __restrict__ bsum, int* cur,
                        int n, int nE) {
    int i = blockIdx.x * blockDim.x + threadIdx.x;
    if (i < n) {
        int v = rowptr[i] + bsum[i >> 10];
        rowptr[i] = v;
        cur[i] = v;
    }
    if (i == 0) rowptr[n] = nE;
}

// ---------------- place edges into packed CSR ----------------
__global__ void k_place(const float* __restrict__ ew, const float* __restrict__ dinv,
                        int nE) {
    int e = blockIdx.x * blockDim.x + threadIdx.x;
    if (e >= nE) return;
    int s = g_src[e], d = g_dst[e];
    int p = atomicAdd(&g_cur[d], 1);
    float norm = ew[e] * dinv[s] * dinv[d];
    g_epack[p] = make_int2(s, __float_as_int(norm));
}

// ---------------- GEMM fout=128 (FFMA2, FMA-pipe bound) ----------------
// 256 thr = 8 warps, 8 rows/warp, 64 rows/block. Ws 64KB + Xs 32KB = 96KB
// -> 2 blocks/SM. x read as broadcast LDS.128 per (r,4k); pairs built via mov.b64.
template <bool RELU>
__global__ void __launch_bounds__(256, 2)
k_gemm128(const float* __restrict__ X, const float* __restrict__ W,
          float* __restrict__ H, int n) {
    extern __shared__ float sm[];
    float* Ws = sm;            // 128*128
    float* Xs = sm + NF * NF;  // 8 warps * 8 rows * 128
    int tid = threadIdx.x, warp = tid >> 5, lane = tid & 31;

    for (int i = tid; i < NF * NF / 4; i += 256)
        ((float4*)Ws)[i] = ((const float4*)W)[i];

    int row0 = blockIdx.x * 64 + warp * 8;
    float* xs = Xs + warp * (8 * NF);
#pragma unroll
    for (int r = 0; r < 8; r++) {
        int row = row0 + r;
        float4 v = make_float4(0.f, 0.f, 0.f, 0.f);
        if (row < n) v = ((const float4*)(X + (size_t)row * NF))[lane];
        if (RELU) {
            v.x = fmaxf(v.x, 0.f); v.y = fmaxf(v.y, 0.f);
            v.z = fmaxf(v.z, 0.f); v.w = fmaxf(v.w, 0.f);
        }
        ((float4*)(xs + r * NF))[lane] = v;
    }
    __syncthreads();

    u64 acc[8][2];
#pragma unroll
    for (int r = 0; r < 8; r++) { acc[r][0] = 0ull; acc[r][1] = 0ull; }

    const float* wl = Ws + 4 * lane;
    for (int k4 = 0; k4 < NF; k4 += 4) {
        float4 xv[8];
#pragma unroll
        for (int r = 0; r < 8; r++)
            xv[r] = *(const float4*)(xs + r * NF + k4);  // broadcast LDS.128
#pragma unroll
        for (int kk = 0; kk < 4; kk++) {
            const float* wp = wl + (k4 + kk) * NF;
            u64 w01 = *(const u64*)(wp);       // LDS.64 pair
            u64 w23 = *(const u64*)(wp + 2);
#pragma unroll
            for (int r = 0; r < 8; r++) {
                float xk = kk == 0 ? xv[r].x : kk == 1 ? xv[r].y
                         : kk == 2 ? xv[r].z : xv[r].w;
                u64 xk2 = dup2(xk);
                ffma2(acc[r][0], xk2, w01);
                ffma2(acc[r][1], xk2, w23);
            }
        }
    }
#pragma unroll
    for (int r = 0; r < 8; r++) {
        int row = row0 + r;
        if (row < n) {
            float2 a = upk2(acc[r][0]), b = upk2(acc[r][1]);
            ((float4*)(H + (size_t)row * NF))[lane] = make_float4(a.x, a.y, b.x, b.y);
        }
    }
}

// ---------------- GEMM fout=40 ----------------
template <bool RELU>
__global__ void __launch_bounds__(256, 2)
k_gemm40(const float* __restrict__ X, const float* __restrict__ W,
         float* __restrict__ H, int n) {
    extern __shared__ float sm[];
    float* Ws = sm;             // 128*40
    float* Xs = sm + NF * FO3;  // 8 warps * 8 rows * 128
    int tid = threadIdx.x, warp = tid >> 5, lane = tid & 31;

    for (int i = tid; i < NF * FO3; i += 256) Ws[i] = W[i];

    int row0 = blockIdx.x * 64 + warp * 8;
    float* xs = Xs + warp * (8 * NF);
#pragma unroll
    for (int r = 0; r < 8; r++) {
        int row = row0 + r;
        float4 v = make_float4(0.f, 0.f, 0.f, 0.f);
        if (row < n) v = ((const float4*)(X + (size_t)row * NF))[lane];
        if (RELU) {
            v.x = fmaxf(v.x, 0.f); v.y = fmaxf(v.y, 0.f);
            v.z = fmaxf(v.z, 0.f); v.w = fmaxf(v.w, 0.f);
        }
        ((float4*)(xs + r * NF))[lane] = v;
    }
    __syncthreads();

    if (lane < 20) {
        u64 acc[8];
#pragma unroll
        for (int r = 0; r < 8; r++) acc[r] = 0ull;

        for (int k4 = 0; k4 < NF; k4 += 4) {
            float4 xv[8];
#pragma unroll
            for (int r = 0; r < 8; r++)
                xv[r] = *(const float4*)(xs + r * NF + k4);
#pragma unroll
            for (int kk = 0; kk < 4; kk++) {
                u64 w2 = *(const u64*)(Ws + (k4 + kk) * FO3 + 2 * lane);
#pragma unroll
                for (int r = 0; r < 8; r++) {
                    float xk = kk == 0 ? xv[r].x : kk == 1 ? xv[r].y
                             : kk == 2 ? xv[r].z : xv[r].w;
                    ffma2(acc[r], dup2(xk), w2);
                }
            }
        }
#pragma unroll
        for (int r = 0; r < 8; r++) {
            int row = row0 + r;
            if (row < n) {
                float2 a = upk2(acc[r]);
                *(float2*)(H + (size_t)row * FO3 + 2 * lane) = a;
            }
        }
    }
}

// ---------------- aggregation (CSR gather, unroll-4, MLP 4) ----------------
__global__ void k_agg128(const float* __restrict__ h, const float* __restrict__ bias,
                         const float* __restrict__ dinv, float* __restrict__ out,
                         int n) {
    int node = (blockIdx.x * blockDim.x + threadIdx.x) >> 5;
    int lane = threadIdx.x & 31;
    if (node >= n) return;
    const float4* h4 = (const float4*)h;
    float dv = dinv[node];
    float selfn = dv * dv;
    float4 sv = __ldg(&h4[(size_t)node * 32 + lane]);
    float4 acc0 = make_float4(sv.x * selfn, sv.y * selfn, sv.z * selfn, sv.w * selfn);
    float4 acc1 = make_float4(0.f, 0.f, 0.f, 0.f);

    int p = g_rowptr[node], p1 = g_rowptr[node + 1];
    for (; p + 4 <= p1; p += 4) {
        int2 e0 = g_epack[p],     e1 = g_epack[p + 1];
        int2 e2 = g_epack[p + 2], e3 = g_epack[p + 3];
        float4 a = __ldg(&h4[(size_t)e0.x * 32 + lane]);
        float4 b = __ldg(&h4[(size_t)e1.x * 32 + lane]);
        float4 c = __ldg(&h4[(size_t)e2.x * 32 + lane]);
        float4 d = __ldg(&h4[(size_t)e3.x * 32 + lane]);
        float n0 = __int_as_float(e0.y), n1 = __int_as_float(e1.y);
        float n2 = __int_as_float(e2.y), n3 = __int_as_float(e3.y);
        acc0.x = fmaf(a.x, n0, acc0.x); acc0.y = fmaf(a.y, n0, acc0.y);
        acc0.z = fmaf(a.z, n0, acc0.z); acc0.w = fmaf(a.w, n0, acc0.w);
        acc1.x = fmaf(b.x, n1, acc1.x); acc1.y = fmaf(b.y, n1, acc1.y);
        acc1.z = fmaf(b.z, n1, acc1.z); acc1.w = fmaf(b.w, n1, acc1.w);
        acc0.x = fmaf(c.x, n2, acc0.x); acc0.y = fmaf(c.y, n2, acc0.y);
        acc0.z = fmaf(c.z, n2, acc0.z); acc0.w = fmaf(c.w, n2, acc0.w);
        acc1.x = fmaf(d.x, n3, acc1.x); acc1.y = fmaf(d.y, n3, acc1.y);
        acc1.z = fmaf(d.z, n3, acc1.z); acc1.w = fmaf(d.w, n3, acc1.w);
    }
    for (; p < p1; p++) {
        int2 e0 = g_epack[p];
        float4 a = __ldg(&h4[(size_t)e0.x * 32 + lane]);
        float n0 = __int_as_float(e0.y);
        acc0.x = fmaf(a.x, n0, acc0.x); acc0.y = fmaf(a.y, n0, acc0.y);
        acc0.z = fmaf(a.z, n0, acc0.z); acc0.w = fmaf(a.w, n0, acc0.w);
    }
    float4 bv = ((const float4*)bias)[lane];
    acc0.x += acc1.x + bv.x; acc0.y += acc1.y + bv.y;
    acc0.z += acc1.z + bv.z; acc0.w += acc1.w + bv.w;
    ((float4*)out)[(size_t)node * 32 + lane] = acc0;
}

__global__ void k_agg40(const float* __restrict__ h, const float* __restrict__ bias,
                        const float* __restrict__ dinv, float* __restrict__ out,
                        int n) {
    int node = (blockIdx.x * blockDim.x + threadIdx.x) >> 5;
    int lane = threadIdx.x & 31;
    if (node >= n || lane >= 20) return;
    const float2* h2 = (const float2*)h;
    float dv = dinv[node];
    float selfn = dv * dv;
    float2 sv = __ldg(&h2[(size_t)node * 20 + lane]);
    float2 acc0 = make_float2(sv.x * selfn, sv.y * selfn);
    float2 acc1 = make_float2(0.f, 0.f);

    int p = g_rowptr[node], p1 = g_rowptr[node + 1];
    for (; p + 4 <= p1; p += 4) {
        int2 e0 = g_epack[p],     e1 = g_epack[p + 1];
        int2 e2 = g_epack[p + 2], e3 = g_epack[p + 3];
        float2 a = __ldg(&h2[(size_t)e0.x * 20 + lane]);
        float2 b = __ldg(&h2[(size_t)e1.x * 20 + lane]);
        float2 c = __ldg(&h2[(size_t)e2.x * 20 + lane]);
        float2 d = __ldg(&h2[(size_t)e3.x * 20 + lane]);
        float n0 = __int_as_float(e0.y), n1 = __int_as_float(e1.y);
        float n2 = __int_as_float(e2.y), n3 = __int_as_float(e3.y);
        acc0.x = fmaf(a.x, n0, acc0.x); acc0.y = fmaf(a.y, n0, acc0.y);
        acc1.x = fmaf(b.x, n1, acc1.x); acc1.y = fmaf(b.y, n1, acc1.y);
        acc0.x = fmaf(c.x, n2, acc0.x); acc0.y = fmaf(c.y, n2, acc0.y);
        acc1.x = fmaf(d.x, n3, acc1.x); acc1.y = fmaf(d.y, n3, acc1.y);
    }
    for (; p < p1; p++) {
        int2 e0 = g_epack[p];
        float2 a = __ldg(&h2[(size_t)e0.x * 20 + lane]);
        float n0 = __int_as_float(e0.y);
        acc0.x = fmaf(a.x, n0, acc0.x); acc0.y = fmaf(a.y, n0, acc0.y);
    }
    float2 bv = ((const float2*)bias)[lane];
    acc0.x += acc1.x + bv.x; acc0.y += acc1.y + bv.y;
    ((float2*)out)[(size_t)node * 20 + lane] = acc0;
}

// ---------------- launch ----------------
extern "C" void kernel_launch(void* const* d_in, const int* in_sizes, int n_in,
                              void* d_out, int out_size) {
    const float* x  = (const float*)d_in[0];
    const void*  ei = d_in[1];
    const float* ew = (const float*)d_in[2];
    const float* W1 = (const float*)d_in[3];
    const float* b1 = (const float*)d_in[4];
    const float* W2 = (const float*)d_in[5];
    const float* b2 = (const float*)d_in[6];
    const float* W3 = (const float*)d_in[7];
    const float* b3 = (const float*)d_in[8];
    int n  = in_sizes[0] / NF;
    int nE = in_sizes[2];
    float* out = (float*)d_out;

    float *dinv, *h, *y;
    int *rowptr, *cur, *cnt, *bsum;
    cudaGetSymbolAddress((void**)&dinv, g_dinv);
    cudaGetSymbolAddress((void**)&h, g_h);
    cudaGetSymbolAddress((void**)&y, g_y);
    cudaGetSymbolAddress((void**)&rowptr, g_rowptr);
    cudaGetSymbolAddress((void**)&cur, g_cur);
    cudaGetSymbolAddress((void**)&cnt, g_cnt);
    cudaGetSymbolAddress((void**)&bsum, g_bsum);

    const int T = 256;
    size_t smem128 = (size_t)(NF * NF + 8 * 8 * NF) * sizeof(float);   // 96 KB
    size_t smem40  = (size_t)(NF * FO3 + 8 * 8 * NF) * sizeof(float);  // 52 KB
    cudaFuncSetAttribute(k_gemm128<false>, cudaFuncAttributeMaxDynamicSharedMemorySize, (int)smem128);
    cudaFuncSetAttribute(k_gemm128<true>,  cudaFuncAttributeMaxDynamicSharedMemorySize, (int)smem128);
    cudaFuncSetAttribute(k_gemm40<true>,   cudaFuncAttributeMaxDynamicSharedMemorySize, (int)smem40);

    // Setup: detect dtype, fused convert+degree+count, dinv, CSR build
    k_flag_init<<<1, 1>>>();
    k_detect<<<(4096 + T - 1) / T, T>>>((const long long*)ei, nE);
    k_init0<<<(n + T - 1) / T, T>>>(dinv, cnt, n);
    k_prep<<<(nE + T - 1) / T, T>>>(ei, ew, dinv, cnt, nE);
    k_dinv<<<(n + T - 1) / T, T>>>(dinv, n);
    int nb = (n + 1023) / 1024;
    k_scanA<<<nb, 1024>>>(cnt, rowptr, bsum, n);
    k_scanB<<<1, 32>>>(bsum, nb);
    k_scanC<<<(n + T - 1) / T, T>>>(rowptr, bsum, cur, n, nE);
    k_place<<<(nE + T - 1) / T, T>>>(ew, dinv, nE);

    int gb = (n + 63) / 64;  // GEMM blocks
    int ab = (n + 7) / 8;    // agg blocks (8 warps/block)

    // Layer 1
    k_gemm128<false><<<gb, T, smem128>>>(x, W1, h, n);
    k_agg128<<<ab, T>>>(h, b1, dinv, y, n);
    // Layer 2 (ReLU fused into GEMM X load)
    k_gemm128<true><<<gb, T, smem128>>>(y, W2, h, n);
    k_agg128<<<ab, T>>>(h, b2, dinv, y, n);
    // Layer 3 (fout=40) -> d_out
    k_gemm40<true><<<gb, T, smem40>>>(y, W3, h, n);
    k_agg40<<<ab, T>>>(h, b3, dinv, out, n);
}

// round 4
// speedup vs baseline: 2.1367x; 1.0432x over previous
#include <cuda_runtime.h>
#include <cuda_fp16.h>
#include <cstdint>

#define NN 100000
#define NE_CAP 1600000
#define NF 128
#define FO3 40

typedef unsigned long long u64;

// ---------------- device scratch (no allocs allowed) ----------------
__device__ float g_dinv[NN];
__device__ float g_h[(size_t)NN * NF];    // fp32 h (layer 3) / raw space
__device__ __half g_hh[(size_t)NN * NF];  // fp16 h (layers 1,2 gather payload)
__device__ float g_y[(size_t)NN * NF];
__device__ int   g_src[NE_CAP];
__device__ int   g_dst[NE_CAP];
__device__ int2  g_epack[NE_CAP];   // CSR-by-dst: {src, f32-bits norm}
__device__ int   g_rowptr[NN + 1];
__device__ int   g_cur[NN];
__device__ int   g_cnt[NN];
__device__ int   g_bsum[1024];
__device__ int   g_is32;

// ---------------- f32x2 helpers (sm_103a FFMA2) ----------------
__device__ __forceinline__ void ffma2(u64& d, u64 a, u64 b) {
    asm("fma.rn.f32x2 %0, %1, %2, %0;" : "+l"(d) : "l"(a), "l"(b));
}
__device__ __forceinline__ u64 dup2(float x) {
    u64 r;
    asm("mov.b64 %0, {%1, %1};" : "=l"(r) : "f"(x));
    return r;
}
__device__ __forceinline__ float2 upk2(u64 v) {
    float2 r;
    asm("mov.b64 {%0, %1}, %2;" : "=f"(r.x), "=f"(r.y) : "l"(v));
    return r;
}

// ---------------- edge dtype detect ----------------
__global__ void k_flag_init() { g_is32 = 0; }

__global__ void k_detect(const long long* __restrict__ raw, int nE) {
    int i = blockIdx.x * blockDim.x + threadIdx.x;
    int lim = nE < 4096 ? nE : 4096;
    if (i < lim) {
        long long v = raw[i];
        if (v < 0 || v >= (1LL << 30)) atomicOr(&g_is32, 1);
    }
}

__global__ void k_init0(float* deg, int* cnt, int n) {
    int i = blockIdx.x * blockDim.x + threadIdx.x;
    if (i < n) { deg[i] = 1.0f; cnt[i] = 0; }
}

// ---------------- fused convert + degree + count ----------------
__global__ void k_prep(const void* __restrict__ raw, const float* __restrict__ ew,
                       float* deg, int* cnt, int nE) {
    int e = blockIdx.x * blockDim.x + threadIdx.x;
    if (e >= nE) return;
    int s, d;
    if (g_is32) {
        const int* p = (const int*)raw;
        s = p[e]; d = p[(size_t)nE + e];
    } else {
        const long long* p = (const long long*)raw;
        s = (int)p[e]; d = (int)p[(size_t)nE + e];
    }
    g_src[e] = s;
    g_dst[e] = d;
    atomicAdd(&deg[d], ew[e]);
    atomicAdd(&cnt[d], 1);
}

__global__ void k_dinv(float* deg, int n) {
    int i = blockIdx.x * blockDim.x + threadIdx.x;
    if (i < n) deg[i] = rsqrtf(deg[i]);
}

// ---------------- exclusive scan cnt -> rowptr ----------------
__global__ void k_scanA(const int* __restrict__ cnt, int* rowptr, int* bsum, int n) {
    __shared__ int s[1024];
    int t = threadIdx.x, i = blockIdx.x * 1024 + t;
    int v = (i < n) ? cnt[i] : 0;
    s[t] = v;
    __syncthreads();
#pragma unroll
    for (int off = 1; off < 1024; off <<= 1) {
        int x = (t >= off) ? s[t - off] : 0;
        __syncthreads();
        s[t] += x;
        __syncthreads();
    }
    if (i < n) rowptr[i] = s[t] - v;
    if (t == 1023) bsum[blockIdx.x] = s[1023];
}

__global__ void k_scanB(int* bsum, int nb) {
    if (threadIdx.x == 0) {
        int run = 0;
        for (int i = 0; i < nb; i++) { int v = bsum[i]; bsum[i] = run; run += v; }
    }
}

__global__ void k_scanC(int* rowptr, const int* __restrict__ bsum, int* cur,
                        int n, int nE) {
    int i = blockIdx.x * blockDim.x + threadIdx.x;
    if (i < n) {
        int v = rowptr[i] + bsum[i >> 10];
        rowptr[i] = v;
        cur[i] = v;
    }
    if (i == 0) rowptr[n] = nE;
}

// ---------------- place edges into packed CSR ----------------
__global__ void k_place(const float* __restrict__ ew, const float* __restrict__ dinv,
                        int nE) {
    int e = blockIdx.x * blockDim.x + threadIdx.x;
    if (e >= nE) return;
    int s = g_src[e], d = g_dst[e];
    int p = atomicAdd(&g_cur[d], 1);
    float norm = ew[e] * dinv[s] * dinv[d];
    g_epack[p] = make_int2(s, __float_as_int(norm));
}

// ---------------- GEMM fout=128 (FFMA2), optional fp16 output ----------------
template <bool RELU, bool HALF_OUT>
__global__ void __launch_bounds__(256, 2)
k_gemm128(const float* __restrict__ X, const float* __restrict__ W,
          float* __restrict__ Hf, __half* __restrict__ Hh, int n) {
    extern __shared__ float sm[];
    float* Ws = sm;            // 128*128
    float* Xs = sm + NF * NF;  // 8 warps * 8 rows * 128
    int tid = threadIdx.x, warp = tid >> 5, lane = tid & 31;

    for (int i = tid; i < NF * NF / 4; i += 256)
        ((float4*)Ws)[i] = ((const float4*)W)[i];

    int row0 = blockIdx.x * 64 + warp * 8;
    float* xs = Xs + warp * (8 * NF);
#pragma unroll
    for (int r = 0; r < 8; r++) {
        int row = row0 + r;
        float4 v = make_float4(0.f, 0.f, 0.f, 0.f);
        if (row < n) v = ((const float4*)(X + (size_t)row * NF))[lane];
        if (RELU) {
            v.x = fmaxf(v.x, 0.f); v.y = fmaxf(v.y, 0.f);
            v.z = fmaxf(v.z, 0.f); v.w = fmaxf(v.w, 0.f);
        }
        ((float4*)(xs + r * NF))[lane] = v;
    }
    __syncthreads();

    u64 acc[8][2];
#pragma unroll
    for (int r = 0; r < 8; r++) { acc[r][0] = 0ull; acc[r][1] = 0ull; }

    const float* wl = Ws + 4 * lane;
    for (int k4 = 0; k4 < NF; k4 += 4) {
        float4 xv[8];
#pragma unroll
        for (int r = 0; r < 8; r++)
            xv[r] = *(const float4*)(xs + r * NF + k4);
#pragma unroll
        for (int kk = 0; kk < 4; kk++) {
            const float* wp = wl + (k4 + kk) * NF;
            u64 w01 = *(const u64*)(wp);
            u64 w23 = *(const u64*)(wp + 2);
#pragma unroll
            for (int r = 0; r < 8; r++) {
                float xk = kk == 0 ? xv[r].x : kk == 1 ? xv[r].y
                         : kk == 2 ? xv[r].z : xv[r].w;
                u64 xk2 = dup2(xk);
                ffma2(acc[r][0], xk2, w01);
                ffma2(acc[r][1], xk2, w23);
            }
        }
    }
#pragma unroll
    for (int r = 0; r < 8; r++) {
        int row = row0 + r;
        if (row < n) {
            float2 a = upk2(acc[r][0]), b = upk2(acc[r][1]);
            if (HALF_OUT) {
                __half2 h01 = __floats2half2_rn(a.x, a.y);
                __half2 h23 = __floats2half2_rn(b.x, b.y);
                uint2 pk = make_uint2(*(unsigned*)&h01, *(unsigned*)&h23);
                ((uint2*)(Hh + (size_t)row * NF))[lane] = pk;
            } else {
                ((float4*)(Hf + (size_t)row * NF))[lane] =
                    make_float4(a.x, a.y, b.x, b.y);
            }
        }
    }
}

// ---------------- GEMM fout=40 (fp32 out, layer 3) ----------------
template <bool RELU>
__global__ void __launch_bounds__(256, 2)
k_gemm40(const float* __restrict__ X, const float* __restrict__ W,
         float* __restrict__ H, int n) {
    extern __shared__ float sm[];
    float* Ws = sm;             // 128*40
    float* Xs = sm + NF * FO3;  // 8 warps * 8 rows * 128
    int tid = threadIdx.x, warp = tid >> 5, lane = tid & 31;

    for (int i = tid; i < NF * FO3; i += 256) Ws[i] = W[i];

    int row0 = blockIdx.x * 64 + warp * 8;
    float* xs = Xs + warp * (8 * NF);
#pragma unroll
    for (int r = 0; r < 8; r++) {
        int row = row0 + r;
        float4 v = make_float4(0.f, 0.f, 0.f, 0.f);
        if (row < n) v = ((const float4*)(X + (size_t)row * NF))[lane];
        if (RELU) {
            v.x = fmaxf(v.x, 0.f); v.y = fmaxf(v.y, 0.f);
            v.z = fmaxf(v.z, 0.f); v.w = fmaxf(v.w, 0.f);
        }
        ((float4*)(xs + r * NF))[lane] = v;
    }
    __syncthreads();

    if (lane < 20) {
        u64 acc[8];
#pragma unroll
        for (int r = 0; r < 8; r++) acc[r] = 0ull;

        for (int k4 = 0; k4 < NF; k4 += 4) {
            float4 xv[8];
#pragma unroll
            for (int r = 0; r < 8; r++)
                xv[r] = *(const float4*)(xs + r * NF + k4);
#pragma unroll
            for (int kk = 0; kk < 4; kk++) {
                u64 w2 = *(const u64*)(Ws + (k4 + kk) * FO3 + 2 * lane);
#pragma unroll
                for (int r = 0; r < 8; r++) {
                    float xk = kk == 0 ? xv[r].x : kk == 1 ? xv[r].y
                             : kk == 2 ? xv[r].z : xv[r].w;
                    ffma2(acc[r], dup2(xk), w2);
                }
            }
        }
#pragma unroll
        for (int r = 0; r < 8; r++) {
            int row = row0 + r;
            if (row < n) {
                float2 a = upk2(acc[r]);
                *(float2*)(H + (size_t)row * FO3 + 2 * lane) = a;
            }
        }
    }
}

// ---------------- aggregation, fp16 gather payload (layers 1,2) ----------------
__global__ void k_agg128h(const __half* __restrict__ h, const float* __restrict__ bias,
                          const float* __restrict__ dinv, float* __restrict__ out,
                          int n) {
    int node = (blockIdx.x * blockDim.x + threadIdx.x) >> 5;
    int lane = threadIdx.x & 31;
    if (node >= n) return;
    const uint2* h2 = (const uint2*)h;  // 32 uint2 (=128 halves) per row
    float dv = dinv[node];
    float selfn = dv * dv;

    uint2 sp = __ldg(&h2[(size_t)node * 32 + lane]);
    float2 s01 = __half22float2(*(const __half2*)&sp.x);
    float2 s23 = __half22float2(*(const __half2*)&sp.y);
    float4 acc0 = make_float4(s01.x * selfn, s01.y * selfn,
                              s23.x * selfn, s23.y * selfn);
    float4 acc1 = make_float4(0.f, 0.f, 0.f, 0.f);

    int p = g_rowptr[node], p1 = g_rowptr[node + 1];
    for (; p + 4 <= p1; p += 4) {
        int2 e0 = g_epack[p],     e1 = g_epack[p + 1];
        int2 e2 = g_epack[p + 2], e3 = g_epack[p + 3];
        uint2 a = __ldg(&h2[(size_t)e0.x * 32 + lane]);
        uint2 b = __ldg(&h2[(size_t)e1.x * 32 + lane]);
        uint2 c = __ldg(&h2[(size_t)e2.x * 32 + lane]);
        uint2 d = __ldg(&h2[(size_t)e3.x * 32 + lane]);
        float n0 = __int_as_float(e0.y), n1 = __int_as_float(e1.y);
        float n2 = __int_as_float(e2.y), n3 = __int_as_float(e3.y);
        float2 a01 = __half22float2(*(const __half2*)&a.x);
        float2 a23 = __half22float2(*(const __half2*)&a.y);
        float2 b01 = __half22float2(*(const __half2*)&b.x);
        float2 b23 = __half22float2(*(const __half2*)&b.y);
        float2 c01 = __half22float2(*(const __half2*)&c.x);
        float2 c23 = __half22float2(*(const __half2*)&c.y);
        float2 d01 = __half22float2(*(const __half2*)&d.x);
        float2 d23 = __half22float2(*(const __half2*)&d.y);
        acc0.x = fmaf(a01.x, n0, acc0.x); acc0.y = fmaf(a01.y, n0, acc0.y);
        acc0.z = fmaf(a23.x, n0, acc0.z); acc0.w = fmaf(a23.y, n0, acc0.w);
        acc1.x = fmaf(b01.x, n1, acc1.x); acc1.y = fmaf(b01.y, n1, acc1.y);
        acc1.z = fmaf(b23.x, n1, acc1.z); acc1.w = fmaf(b23.y, n1, acc1.w);
        acc0.x = fmaf(c01.x, n2, acc0.x); acc0.y = fmaf(c01.y, n2, acc0.y);
        acc0.z = fmaf(c23.x, n2, acc0.z); acc0.w = fmaf(c23.y, n2, acc0.w);
        acc1.x = fmaf(d01.x, n3, acc1.x); acc1.y = fmaf(d01.y, n3, acc1.y);
        acc1.z = fmaf(d23.x, n3, acc1.z); acc1.w = fmaf(d23.y, n3, acc1.w);
    }
    for (; p < p1; p++) {
        int2 e0 = g_epack[p];
        uint2 a = __ldg(&h2[(size_t)e0.x * 32 + lane]);
        float n0 = __int_as_float(e0.y);
        float2 a01 = __half22float2(*(const __half2*)&a.x);
        float2 a23 = __half22float2(*(const __half2*)&a.y);
        acc0.x = fmaf(a01.x, n0, acc0.x); acc0.y = fmaf(a01.y, n0, acc0.y);
        acc0.z = fmaf(a23.x, n0, acc0.z); acc0.w = fmaf(a23.y, n0, acc0.w);
    }
    float4 bv = ((const float4*)bias)[lane];
    acc0.x += acc1.x + bv.x; acc0.y += acc1.y + bv.y;
    acc0.z += acc1.z + bv.z; acc0.w += acc1.w + bv.w;
    ((float4*)out)[(size_t)node * 32 + lane] = acc0;
}

// ---------------- aggregation fp32, fout=40 (layer 3, final output) ----------------
__global__ void k_agg40(const float* __restrict__ h, const float* __restrict__ bias,
                        const float* __restrict__ dinv, float* __restrict__ out,
                        int n) {
    int node = (blockIdx.x * blockDim.x + threadIdx.x) >> 5;
    int lane = threadIdx.x & 31;
    if (node >= n || lane >= 20) return;
    const float2* h2 = (const float2*)h;
    float dv = dinv[node];
    float selfn = dv * dv;
    float2 sv = __ldg(&h2[(size_t)node * 20 + lane]);
    float2 acc0 = make_float2(sv.x * selfn, sv.y * selfn);
    float2 acc1 = make_float2(0.f, 0.f);

    int p = g_rowptr[node], p1 = g_rowptr[node + 1];
    for (; p + 4 <= p1; p += 4) {
        int2 e0 = g_epack[p],     e1 = g_epack[p + 1];
        int2 e2 = g_epack[p + 2], e3 = g_epack[p + 3];
        float2 a = __ldg(&h2[(size_t)e0.x * 20 + lane]);
        float2 b = __ldg(&h2[(size_t)e1.x * 20 + lane]);
        float2 c = __ldg(&h2[(size_t)e2.x * 20 + lane]);
        float2 d = __ldg(&h2[(size_t)e3.x * 20 + lane]);
        float n0 = __int_as_float(e0.y), n1 = __int_as_float(e1.y);
        float n2 = __int_as_float(e2.y), n3 = __int_as_float(e3.y);
        acc0.x = fmaf(a.x, n0, acc0.x); acc0.y = fmaf(a.y, n0, acc0.y);
        acc1.x = fmaf(b.x, n1, acc1.x); acc1.y = fmaf(b.y, n1, acc1.y);
        acc0.x = fmaf(c.x, n2, acc0.x); acc0.y = fmaf(c.y, n2, acc0.y);
        acc1.x = fmaf(d.x, n3, acc1.x); acc1.y = fmaf(d.y, n3, acc1.y);
    }
    for (; p < p1; p++) {
        int2 e0 = g_epack[p];
        float2 a = __ldg(&h2[(size_t)e0.x * 20 + lane]);
        float n0 = __int_as_float(e0.y);
        acc0.x = fmaf(a.x, n0, acc0.x); acc0.y = fmaf(a.y, n0, acc0.y);
    }
    float2 bv = ((const float2*)bias)[lane];
    acc0.x += acc1.x + bv.x; acc0.y += acc1.y + bv.y;
    ((float2*)out)[(size_t)node * 20 + lane] = acc0;
}

// ---------------- launch ----------------
extern "C" void kernel_launch(void* const* d_in, const int* in_sizes, int n_in,
                              void* d_out, int out_size) {
    const float* x  = (const float*)d_in[0];
    const void*  ei = d_in[1];
    const float* ew = (const float*)d_in[2];
    const float* W1 = (const float*)d_in[3];
    const float* b1 = (const float*)d_in[4];
    const float* W2 = (const float*)d_in[5];
    const float* b2 = (const float*)d_in[6];
    const float* W3 = (const float*)d_in[7];
    const float* b3 = (const float*)d_in[8];
    int n  = in_sizes[0] / NF;
    int nE = in_sizes[2];
    float* out = (float*)d_out;

    float *dinv, *h, *y;
    __half* hh;
    int *rowptr, *cur, *cnt, *bsum;
    cudaGetSymbolAddress((void**)&dinv, g_dinv);
    cudaGetSymbolAddress((void**)&h, g_h);
    cudaGetSymbolAddress((void**)&hh, g_hh);
    cudaGetSymbolAddress((void**)&y, g_y);
    cudaGetSymbolAddress((void**)&rowptr, g_rowptr);
    cudaGetSymbolAddress((void**)&cur, g_cur);
    cudaGetSymbolAddress((void**)&cnt, g_cnt);
    cudaGetSymbolAddress((void**)&bsum, g_bsum);

    const int T = 256;
    size_t smem128 = (size_t)(NF * NF + 8 * 8 * NF) * sizeof(float);   // 96 KB
    size_t smem40  = (size_t)(NF * FO3 + 8 * 8 * NF) * sizeof(float);  // 52 KB
    cudaFuncSetAttribute(k_gemm128<false, true>, cudaFuncAttributeMaxDynamicSharedMemorySize, (int)smem128);
    cudaFuncSetAttribute(k_gemm128<true, true>,  cudaFuncAttributeMaxDynamicSharedMemorySize, (int)smem128);
    cudaFuncSetAttribute(k_gemm40<true>,   cudaFuncAttributeMaxDynamicSharedMemorySize, (int)smem40);

    // Setup: detect dtype, fused convert+degree+count, dinv, CSR build
    k_flag_init<<<1, 1>>>();
    k_detect<<<(4096 + T - 1) / T, T>>>((const long long*)ei, nE);
    k_init0<<<(n + T - 1) / T, T>>>(dinv, cnt, n);
    k_prep<<<(nE + T - 1) / T, T>>>(ei, ew, dinv, cnt, nE);
    k_dinv<<<(n + T - 1) / T, T>>>(dinv, n);
    int nb = (n + 1023) / 1024;
    k_scanA<<<nb, 1024>>>(cnt, rowptr, bsum, n);
    k_scanB<<<1, 32>>>(bsum, nb);
    k_scanC<<<(n + T - 1) / T, T>>>(rowptr, bsum, cur, n, nE);
    k_place<<<(nE + T - 1) / T, T>>>(ew, dinv, nE);

    int gb = (n + 63) / 64;  // GEMM blocks
    int ab = (n + 7) / 8;    // agg blocks (8 warps/block)

    // Layer 1: GEMM -> fp16 h, agg fp16-gather -> fp32 y
    k_gemm128<false, true><<<gb, T, smem128>>>(x, W1, nullptr, hh, n);
    k_agg128h<<<ab, T>>>(hh, b1, dinv, y, n);
    // Layer 2 (ReLU fused into GEMM X load)
    k_gemm128<true, true><<<gb, T, smem128>>>(y, W2, nullptr, hh, n);
    k_agg128h<<<ab, T>>>(hh, b2, dinv, y, n);
    // Layer 3: all fp32 -> d_out
    k_gemm40<true><<<gb, T, smem40>>>(y, W3, h, n);
    k_agg40<<<ab, T>>>(h, b3, dinv, out, n);
}

// round 5
// speedup vs baseline: 2.2732x; 1.0639x over previous
#include <cuda_runtime.h>
#include <cuda_fp16.h>
#include <cstdint>

#define NN 100000
#define NE_CAP 1600000
#define NF 128
#define FO3 40

typedef unsigned long long u64;

// ---------------- device scratch (no allocs allowed) ----------------
__device__ float  g_deg[NN];               // weighted deg (excl self) -> dinv in place
__device__ __half g_hh[(size_t)NN * NF];   // fp16 h (layers 1,2 gather payload)
__device__ float  g_h32[(size_t)NN * NF];  // fp32 h (layer 3)
__device__ __half g_yh[(size_t)NN * NF];   // fp16 y (layer 1,2 agg outputs)
__device__ int2   g_sd[NE_CAP];            // packed {src,dst}
__device__ int2   g_epack[NE_CAP];         // CSR-by-dst {src, f32-bits norm}
__device__ int    g_rowptr[NN + 1];
__device__ int    g_cur[NN];
__device__ int    g_cnt[NN];
__device__ int    g_bsum[128];
__device__ int    g_is32;

// ---------------- f32x2 helpers (sm_103a FFMA2) ----------------
__device__ __forceinline__ void ffma2(u64& d, u64 a, u64 b) {
    asm("fma.rn.f32x2 %0, %1, %2, %0;" : "+l"(d) : "l"(a), "l"(b));
}
__device__ __forceinline__ u64 dup2(float x) {
    u64 r;
    asm("mov.b64 %0, {%1, %1};" : "=l"(r) : "f"(x));
    return r;
}
__device__ __forceinline__ float2 upk2(u64 v) {
    float2 r;
    asm("mov.b64 {%0, %1}, %2;" : "=f"(r.x), "=f"(r.y) : "l"(v));
    return r;
}

// ---------------- edge dtype detect (g_is32 pre-zeroed via memset) ----------------
__global__ void k_detect(const long long* __restrict__ raw, int nE) {
    int i = blockIdx.x * blockDim.x + threadIdx.x;
    int lim = nE < 4096 ? nE : 4096;
    if (i < lim) {
        long long v = raw[i];
        if (v < 0 || v >= (1LL << 30)) atomicOr(&g_is32, 1);
    }
}

// ---------------- fused convert + degree + count ----------------
__global__ void k_prep(const void* __restrict__ raw, const float* __restrict__ ew,
                       float* deg, int* cnt, int nE) {
    int e = blockIdx.x * blockDim.x + threadIdx.x;
    if (e >= nE) return;
    int s, d;
    if (g_is32) {
        const int* p = (const int*)raw;
        s = p[e]; d = p[(size_t)nE + e];
    } else {
        const long long* p = (const long long*)raw;
        s = (int)p[e]; d = (int)p[(size_t)nE + e];
    }
    g_sd[e] = make_int2(s, d);
    atomicAdd(&deg[d], ew[e]);
    atomicAdd(&cnt[d], 1);
}

__global__ void k_dinv(float* deg, int n) {
    int i = blockIdx.x * blockDim.x + threadIdx.x;
    if (i < n) deg[i] = rsqrtf(deg[i] + 1.0f);  // +1 = self-loop weight
}

// ---------------- exclusive scan cnt -> rowptr ----------------
__global__ void k_scanA(const int* __restrict__ cnt, int* rowptr, int* bsum, int n) {
    __shared__ int s[1024];
    int t = threadIdx.x, i = blockIdx.x * 1024 + t;
    int v = (i < n) ? cnt[i] : 0;
    s[t] = v;
    __syncthreads();
#pragma unroll
    for (int off = 1; off < 1024; off <<= 1) {
        int x = (t >= off) ? s[t - off] : 0;
        __syncthreads();
        s[t] += x;
        __syncthreads();
    }
    if (i < n) rowptr[i] = s[t] - v;
    if (t == 1023) bsum[blockIdx.x] = s[1023];
}

__global__ void k_scanB(int* bsum, int nb) {  // parallel exclusive scan, nb <= 128
    __shared__ int s[128];
    int t = threadIdx.x;
    int v = (t < nb) ? bsum[t] : 0;
    s[t] = v;
    __syncthreads();
#pragma unroll
    for (int off = 1; off < 128; off <<= 1) {
        int x = (t >= off) ? s[t - off] : 0;
        __syncthreads();
        s[t] += x;
        __syncthreads();
    }
    if (t < nb) bsum[t] = s[t] - v;
}

__global__ void k_scanC(int* rowptr, const int* __restrict__ bsum, int* cur,
                        int n, int nE) {
    int i = blockIdx.x * blockDim.x + threadIdx.x;
    if (i < n) {
        int v = rowptr[i] + bsum[i >> 10];
        rowptr[i] = v;
        cur[i] = v;
    }
    if (i == 0) rowptr[n] = nE;
}

// ---------------- place edges into packed CSR ----------------
__global__ void k_place(const float* __restrict__ ew, const float* __restrict__ dinv,
                        int nE) {
    int e = blockIdx.x * blockDim.x + threadIdx.x;
    if (e >= nE) return;
    int2 sd = g_sd[e];
    int p = atomicAdd(&g_cur[sd.y], 1);
    float norm = ew[e] * dinv[sd.x] * dinv[sd.y];
    g_epack[p] = make_int2(sd.x, __float_as_int(norm));
}

// ---------------- templated row loader ----------------
template <bool RELU>
__device__ __forceinline__ float4 ld_row4(const float* X, size_t rowoff, int lane) {
    float4 v = ((const float4*)(X + rowoff))[lane];
    if (RELU) {
        v.x = fmaxf(v.x, 0.f); v.y = fmaxf(v.y, 0.f);
        v.z = fmaxf(v.z, 0.f); v.w = fmaxf(v.w, 0.f);
    }
    return v;
}
template <bool RELU>
__device__ __forceinline__ float4 ld_row4(const __half* X, size_t rowoff, int lane) {
    uint2 p = ((const uint2*)(X + rowoff))[lane];
    float2 a = __half22float2(*(const __half2*)&p.x);
    float2 b = __half22float2(*(const __half2*)&p.y);
    float4 v = make_float4(a.x, a.y, b.x, b.y);
    if (RELU) {
        v.x = fmaxf(v.x, 0.f); v.y = fmaxf(v.y, 0.f);
        v.z = fmaxf(v.z, 0.f); v.w = fmaxf(v.w, 0.f);
    }
    return v;
}

// ---------------- GEMM fout=128 (FFMA2) -> fp16 h ----------------
template <bool RELU, typename TIN>
__global__ void __launch_bounds__(256, 2)
k_gemm128(const TIN* __restrict__ X, const float* __restrict__ W,
          __half* __restrict__ Hh, int n) {
    extern __shared__ float sm[];
    float* Ws = sm;            // 128*128
    float* Xs = sm + NF * NF;  // 8 warps * 8 rows * 128
    int tid = threadIdx.x, warp = tid >> 5, lane = tid & 31;

    for (int i = tid; i < NF * NF / 4; i += 256)
        ((float4*)Ws)[i] = ((const float4*)W)[i];

    int row0 = blockIdx.x * 64 + warp * 8;
    float* xs = Xs + warp * (8 * NF);
#pragma unroll
    for (int r = 0; r < 8; r++) {
        int row = row0 + r;
        float4 v = make_float4(0.f, 0.f, 0.f, 0.f);
        if (row < n) v = ld_row4<RELU>(X, (size_t)row * NF, lane);
        ((float4*)(xs + r * NF))[lane] = v;
    }
    __syncthreads();

    u64 acc[8][2];
#pragma unroll
    for (int r = 0; r < 8; r++) { acc[r][0] = 0ull; acc[r][1] = 0ull; }

    const float* wl = Ws + 4 * lane;
    for (int k4 = 0; k4 < NF; k4 += 4) {
        float4 xv[8];
#pragma unroll
        for (int r = 0; r < 8; r++)
            xv[r] = *(const float4*)(xs + r * NF + k4);
#pragma unroll
        for (int kk = 0; kk < 4; kk++) {
            const float* wp = wl + (k4 + kk) * NF;
            u64 w01 = *(const u64*)(wp);
            u64 w23 = *(const u64*)(wp + 2);
#pragma unroll
            for (int r = 0; r < 8; r++) {
                float xk = kk == 0 ? xv[r].x : kk == 1 ? xv[r].y
                         : kk == 2 ? xv[r].z : xv[r].w;
                u64 xk2 = dup2(xk);
                ffma2(acc[r][0], xk2, w01);
                ffma2(acc[r][1], xk2, w23);
            }
        }
    }
#pragma unroll
    for (int r = 0; r < 8; r++) {
        int row = row0 + r;
        if (row < n) {
            float2 a = upk2(acc[r][0]), b = upk2(acc[r][1]);
            __half2 h01 = __floats2half2_rn(a.x, a.y);
            __half2 h23 = __floats2half2_rn(b.x, b.y);
            ((uint2*)(Hh + (size_t)row * NF))[lane] =
                make_uint2(*(unsigned*)&h01, *(unsigned*)&h23);
        }
    }
}

// ---------------- GEMM fout=40 (fp16 in, fp32 out; layer 3) ----------------
template <bool RELU, typename TIN>
__global__ void __launch_bounds__(256, 2)
k_gemm40(const TIN* __restrict__ X, const float* __restrict__ W,
         float* __restrict__ H, int n) {
    extern __shared__ float sm[];
    float* Ws = sm;             // 128*40
    float* Xs = sm + NF * FO3;  // 8 warps * 8 rows * 128
    int tid = threadIdx.x, warp = tid >> 5, lane = tid & 31;

    for (int i = tid; i < NF * FO3; i += 256) Ws[i] = W[i];

    int row0 = blockIdx.x * 64 + warp * 8;
    float* xs = Xs + warp * (8 * NF);
#pragma unroll
    for (int r = 0; r < 8; r++) {
        int row = row0 + r;
        float4 v = make_float4(0.f, 0.f, 0.f, 0.f);
        if (row < n) v = ld_row4<RELU>(X, (size_t)row * NF, lane);
        ((float4*)(xs + r * NF))[lane] = v;
    }
    __syncthreads();

    if (lane < 20) {
        u64 acc[8];
#pragma unroll
        for (int r = 0; r < 8; r++) acc[r] = 0ull;

        for (int k4 = 0; k4 < NF; k4 += 4) {
            float4 xv[8];
#pragma unroll
            for (int r = 0; r < 8; r++)
                xv[r] = *(const float4*)(xs + r * NF + k4);
#pragma unroll
            for (int kk = 0; kk < 4; kk++) {
                u64 w2 = *(const u64*)(Ws + (k4 + kk) * FO3 + 2 * lane);
#pragma unroll
                for (int r = 0; r < 8; r++) {
                    float xk = kk == 0 ? xv[r].x : kk == 1 ? xv[r].y
                             : kk == 2 ? xv[r].z : xv[r].w;
                    ffma2(acc[r], dup2(xk), w2);
                }
            }
        }
#pragma unroll
        for (int r = 0; r < 8; r++) {
            int row = row0 + r;
            if (row < n) {
                float2 a = upk2(acc[r]);
                *(float2*)(H + (size_t)row * FO3 + 2 * lane) = a;
            }
        }
    }
}

// ---------------- aggregation, fp16 gather -> fp16 y (layers 1,2) ----------------
__global__ void k_agg128h(const __half* __restrict__ h, const float* __restrict__ bias,
                          const float* __restrict__ dinv, __half* __restrict__ outh,
                          int n) {
    int node = (blockIdx.x * blockDim.x + threadIdx.x) >> 5;
    int lane = threadIdx.x & 31;
    if (node >= n) return;
    const uint2* h2 = (const uint2*)h;
    float dv = dinv[node];
    float selfn = dv * dv;

    uint2 sp = __ldg(&h2[(size_t)node * 32 + lane]);
    float2 s01 = __half22float2(*(const __half2*)&sp.x);
    float2 s23 = __half22float2(*(const __half2*)&sp.y);
    float4 acc0 = make_float4(s01.x * selfn, s01.y * selfn,
                              s23.x * selfn, s23.y * selfn);
    float4 acc1 = make_float4(0.f, 0.f, 0.f, 0.f);

    int p = g_rowptr[node], p1 = g_rowptr[node + 1];
    for (; p + 4 <= p1; p += 4) {
        int2 e0 = g_epack[p],     e1 = g_epack[p + 1];
        int2 e2 = g_epack[p + 2], e3 = g_epack[p + 3];
        uint2 a = __ldg(&h2[(size_t)e0.x * 32 + lane]);
        uint2 b = __ldg(&h2[(size_t)e1.x * 32 + lane]);
        uint2 c = __ldg(&h2[(size_t)e2.x * 32 + lane]);
        uint2 d = __ldg(&h2[(size_t)e3.x * 32 + lane]);
        float n0 = __int_as_float(e0.y), n1 = __int_as_float(e1.y);
        float n2 = __int_as_float(e2.y), n3 = __int_as_float(e3.y);
        float2 a01 = __half22float2(*(const __half2*)&a.x);
        float2 a23 = __half22float2(*(const __half2*)&a.y);
        float2 b01 = __half22float2(*(const __half2*)&b.x);
        float2 b23 = __half22float2(*(const __half2*)&b.y);
        float2 c01 = __half22float2(*(const __half2*)&c.x);
        float2 c23 = __half22float2(*(const __half2*)&c.y);
        float2 d01 = __half22float2(*(const __half2*)&d.x);
        float2 d23 = __half22float2(*(const __half2*)&d.y);
        acc0.x = fmaf(a01.x, n0, acc0.x); acc0.y = fmaf(a01.y, n0, acc0.y);
        acc0.z = fmaf(a23.x, n0, acc0.z); acc0.w = fmaf(a23.y, n0, acc0.w);
        acc1.x = fmaf(b01.x, n1, acc1.x); acc1.y = fmaf(b01.y, n1, acc1.y);
        acc1.z = fmaf(b23.x, n1, acc1.z); acc1.w = fmaf(b23.y, n1, acc1.w);
        acc0.x = fmaf(c01.x, n2, acc0.x); acc0.y = fmaf(c01.y, n2, acc0.y);
        acc0.z = fmaf(c23.x, n2, acc0.z); acc0.w = fmaf(c23.y, n2, acc0.w);
        acc1.x = fmaf(d01.x, n3, acc1.x); acc1.y = fmaf(d01.y, n3, acc1.y);
        acc1.z = fmaf(d23.x, n3, acc1.z); acc1.w = fmaf(d23.y, n3, acc1.w);
    }
    for (; p < p1; p++) {
        int2 e0 = g_epack[p];
        uint2 a = __ldg(&h2[(size_t)e0.x * 32 + lane]);
        float n0 = __int_as_float(e0.y);
        float2 a01 = __half22float2(*(const __half2*)&a.x);
        float2 a23 = __half22float2(*(const __half2*)&a.y);
        acc0.x = fmaf(a01.x, n0, acc0.x); acc0.y = fmaf(a01.y, n0, acc0.y);
        acc0.z = fmaf(a23.x, n0, acc0.z); acc0.w = fmaf(a23.y, n0, acc0.w);
    }
    float4 bv = ((const float4*)bias)[lane];
    acc0.x += acc1.x + bv.x; acc0.y += acc1.y + bv.y;
    acc0.z += acc1.z + bv.z; acc0.w += acc1.w + bv.w;
    __half2 o01 = __floats2half2_rn(acc0.x, acc0.y);
    __half2 o23 = __floats2half2_rn(acc0.z, acc0.w);
    ((uint2*)outh)[(size_t)node * 32 + lane] =
        make_uint2(*(unsigned*)&o01, *(unsigned*)&o23);
}

// ---------------- aggregation fp32, fout=40 (layer 3, final) ----------------
__global__ void k_agg40(const float* __restrict__ h, const float* __restrict__ bias,
                        const float* __restrict__ dinv, float* __restrict__ out,
                        int n) {
    int node = (blockIdx.x * blockDim.x + threadIdx.x) >> 5;
    int lane = threadIdx.x & 31;
    if (node >= n || lane >= 20) return;
    const float2* h2 = (const float2*)h;
    float dv = dinv[node];
    float selfn = dv * dv;
    float2 sv = __ldg(&h2[(size_t)node * 20 + lane]);
    float2 acc0 = make_float2(sv.x * selfn, sv.y * selfn);
    float2 acc1 = make_float2(0.f, 0.f);

    int p = g_rowptr[node], p1 = g_rowptr[node + 1];
    for (; p + 4 <= p1; p += 4) {
        int2 e0 = g_epack[p],     e1 = g_epack[p + 1];
        int2 e2 = g_epack[p + 2], e3 = g_epack[p + 3];
        float2 a = __ldg(&h2[(size_t)e0.x * 20 + lane]);
        float2 b = __ldg(&h2[(size_t)e1.x * 20 + lane]);
        float2 c = __ldg(&h2[(size_t)e2.x * 20 + lane]);
        float2 d = __ldg(&h2[(size_t)e3.x * 20 + lane]);
        float n0 = __int_as_float(e0.y), n1 = __int_as_float(e1.y);
        float n2 = __int_as_float(e2.y), n3 = __int_as_float(e3.y);
        acc0.x = fmaf(a.x, n0, acc0.x); acc0.y = fmaf(a.y, n0, acc0.y);
        acc1.x = fmaf(b.x, n1, acc1.x); acc1.y = fmaf(b.y, n1, acc1.y);
        acc0.x = fmaf(c.x, n2, acc0.x); acc0.y = fmaf(c.y, n2, acc0.y);
        acc1.x = fmaf(d.x, n3, acc1.x); acc1.y = fmaf(d.y, n3, acc1.y);
    }
    for (; p < p1; p++) {
        int2 e0 = g_epack[p];
        float2 a = __ldg(&h2[(size_t)e0.x * 20 + lane]);
        float n0 = __int_as_float(e0.y);
        acc0.x = fmaf(a.x, n0, acc0.x); acc0.y = fmaf(a.y, n0, acc0.y);
    }
    float2 bv = ((const float2*)bias)[lane];
    acc0.x += acc1.x + bv.x; acc0.y += acc1.y + bv.y;
    ((float2*)out)[(size_t)node * 20 + lane] = acc0;
}

// ---------------- launch ----------------
extern "C" void kernel_launch(void* const* d_in, const int* in_sizes, int n_in,
                              void* d_out, int out_size) {
    const float* x  = (const float*)d_in[0];
    const void*  ei = d_in[1];
    const float* ew = (const float*)d_in[2];
    const float* W1 = (const float*)d_in[3];
    const float* b1 = (const float*)d_in[4];
    const float* W2 = (const float*)d_in[5];
    const float* b2 = (const float*)d_in[6];
    const float* W3 = (const float*)d_in[7];
    const float* b3 = (const float*)d_in[8];
    int n  = in_sizes[0] / NF;
    int nE = in_sizes[2];
    float* out = (float*)d_out;

    float *dinv, *h32;
    __half *hh, *yh;
    int *rowptr, *cur, *cnt, *bsum, *is32p;
    cudaGetSymbolAddress((void**)&dinv, g_deg);
    cudaGetSymbolAddress((void**)&hh, g_hh);
    cudaGetSymbolAddress((void**)&h32, g_h32);
    cudaGetSymbolAddress((void**)&yh, g_yh);
    cudaGetSymbolAddress((void**)&rowptr, g_rowptr);
    cudaGetSymbolAddress((void**)&cur, g_cur);
    cudaGetSymbolAddress((void**)&cnt, g_cnt);
    cudaGetSymbolAddress((void**)&bsum, g_bsum);
    cudaGetSymbolAddress((void**)&is32p, g_is32);

    const int T = 256;
    size_t smem128 = (size_t)(NF * NF + 8 * 8 * NF) * sizeof(float);   // 96 KB
    size_t smem40  = (size_t)(NF * FO3 + 8 * 8 * NF) * sizeof(float);  // 52 KB
    cudaFuncSetAttribute(k_gemm128<false, float>,  cudaFuncAttributeMaxDynamicSharedMemorySize, (int)smem128);
    cudaFuncSetAttribute(k_gemm128<true, __half>,  cudaFuncAttributeMaxDynamicSharedMemorySize, (int)smem128);
    cudaFuncSetAttribute(k_gemm40<true, __half>,   cudaFuncAttributeMaxDynamicSharedMemorySize, (int)smem40);

    int gb = (n + 63) / 64;  // GEMM blocks
    int ab = (n + 7) / 8;    // agg blocks (8 warps/block)
    int nb = (n + 1023) / 1024;

    // Fork stream: GEMM1 (x@W1 -> hh) is independent of all edge setup.
    cudaStream_t s2;
    cudaStreamCreateWithFlags(&s2, cudaStreamNonBlocking);
    cudaEvent_t evF, evJ;
    cudaEventCreateWithFlags(&evF, cudaEventDisableTiming);
    cudaEventCreateWithFlags(&evJ, cudaEventDisableTiming);

    cudaEventRecord(evF, 0);
    cudaStreamWaitEvent(s2, evF, 0);
    k_gemm128<false, float><<<gb, T, smem128, s2>>>(x, W1, hh, n);
    cudaEventRecord(evJ, s2);

    // Edge setup on the main stream (overlapped with GEMM1)
    cudaMemsetAsync(is32p, 0, sizeof(int), 0);
    cudaMemsetAsync(cnt, 0, (size_t)n * sizeof(int), 0);
    cudaMemsetAsync(dinv, 0, (size_t)n * sizeof(float), 0);  // deg accumulates from 0
    k_detect<<<(4096 + T - 1) / T, T>>>((const long long*)ei, nE);
    k_prep<<<(nE + T - 1) / T, T>>>(ei, ew, dinv, cnt, nE);
    k_dinv<<<(n + T - 1) / T, T>>>(dinv, n);
    k_scanA<<<nb, 1024>>>(cnt, rowptr, bsum, n);
    k_scanB<<<1, 128>>>(bsum, nb);
    k_scanC<<<(n + T - 1) / T, T>>>(rowptr, bsum, cur, n, nE);
    k_place<<<(nE + T - 1) / T, T>>>(ew, dinv, nE);

    // Join: aggregation needs both CSR (main) and GEMM1 (s2)
    cudaStreamWaitEvent(0, evJ, 0);

    // Layer 1
    k_agg128h<<<ab, T>>>(hh, b1, dinv, yh, n);
    // Layer 2 (ReLU fused into GEMM X load)
    k_gemm128<true, __half><<<gb, T, smem128>>>(yh, W2, hh, n);
    k_agg128h<<<ab, T>>>(hh, b2, dinv, yh, n);
    // Layer 3: fp16 in -> fp32 compute -> d_out
    k_gemm40<true, __half><<<gb, T, smem40>>>(yh, W3, h32, n);
    k_agg40<<<ab, T>>>(h32, b3, dinv, out, n);
    // NOTE: s2/evF/evJ are intentionally not destroyed here — destroying a
    // stream/event that participates in an active capture invalidates the graph.
}